// round 8
// baseline (speedup 1.0000x reference)
#include <cuda_runtime.h>

// StreamNet_K3_S1: fused halo-concat + 3x3 VALID conv + bias.
// x:[8,32,256,256] rbuf:[8,32,256,2] bbuf:[8,32,2,258] W:[32,32,3,3] bias:[32]
// out:[8,32,256,256]
//
// R7: packed fp32 math via fma.rn.f32x2 (FFMA2) — 2 FMAs per issue slot.
// Same tiling as R6 (8x32 tile, 256 thr, thread = 1 c_out x 8 rows x 4 cols),
// accumulators and input window held as 64-bit f32x2 pairs.

#define BATCH 8
#define CH 32
#define P 256
#define PP (P + 2)

#define TH 8              // output rows per block
#define TW 32             // output cols per block
#define IN_H (TH + 2)     // 10 padded rows in tile
#define IN_W (TW + 2)     // 34 padded cols in tile
#define IN_WP 36          // smem row stride (floats), keeps 16B alignment
#define W_STRIDE 289      // 32*9 + 1 pad -> co-delta maps to distinct banks

#define SMEM_IN_FLOATS (CH * IN_H * IN_WP)   // 11520
#define SMEM_W_FLOATS  (CH * W_STRIDE)       // 9248
#define SMEM_BYTES ((SMEM_IN_FLOATS + SMEM_W_FLOATS) * 4)  // 83072 B

typedef unsigned long long u64;

// pack two f32 into an f32x2 register pair
__device__ __forceinline__ u64 pk(float lo, float hi) {
    u64 r;
    asm("mov.b64 %0, {%1, %2};" : "=l"(r) : "f"(lo), "f"(hi));
    return r;
}
__device__ __forceinline__ void upk(float& lo, float& hi, u64 v) {
    asm("mov.b64 {%0, %1}, %2;" : "=f"(lo), "=f"(hi) : "l"(v));
}
// packed dual fp32 FMA: d = a*b + c (elementwise on the two lanes)
__device__ __forceinline__ u64 f2fma(u64 a, u64 b, u64 c) {
    u64 d;
    asm("fma.rn.f32x2 %0, %1, %2, %3;" : "=l"(d) : "l"(a), "l"(b), "l"(c));
    return d;
}

__global__ __launch_bounds__(256, 2)
void streamnet_conv3x3_kernel(const float* __restrict__ x,
                              const float* __restrict__ rbuf,
                              const float* __restrict__ bbuf,
                              const float* __restrict__ Wt,
                              const float* __restrict__ bias,
                              float* __restrict__ out)
{
    extern __shared__ float smem[];
    float* sIn = smem;                       // [CH][IN_H][IN_WP]
    float* sW  = smem + SMEM_IN_FLOATS;      // [CH][W_STRIDE]

    const int tid   = threadIdx.x;
    const int b     = blockIdx.z;
    const int r0    = blockIdx.y * TH;       // output row base
    const int c0blk = blockIdx.x * TW;       // output col base

    // ---- load all weights into smem (9216 elems), padded stride ----
    #pragma unroll 4
    for (int i = tid; i < CH * CH * 9; i += 256) {
        int co   = i / 288;
        int rest = i - co * 288;             // ci*9 + k
        sW[co * W_STRIDE + rest] = Wt[i];
    }

    // ---- load padded input tile: 32ci x 10 x 34, halo-mapped ----
    for (int t = tid; t < CH * IN_H * IN_W; t += 256) {
        int ci   = t / (IN_H * IN_W);
        int rem  = t - ci * (IN_H * IN_W);
        int y    = rem / IN_W;
        int xcol = rem - y * IN_W;
        int pr   = r0 + y;                   // padded row  [0, 258)
        int pc   = c0blk + xcol;             // padded col  [0, 258)
        float v;
        if (pr < 2) {
            v = bbuf[((b * CH + ci) * 2 + pr) * PP + pc];
        } else {
            int xr = pr - 2;
            if (pc < 2) {
                v = rbuf[((b * CH + ci) * P + xr) * 2 + pc];
            } else {
                int xc = pc - 2;
                v = (xc == P - 1) ? 0.0f
                                  : x[((size_t)(b * CH + ci) * P + xr) * P + xc];
            }
        }
        sIn[ci * (IN_H * IN_WP) + y * IN_WP + xcol] = v;
    }
    __syncthreads();

    // ---- compute: each thread = 1 c_out, 8 rows x 4 cols (2 f32x2 pairs) ----
    const int co = tid >> 3;
    const int c0 = (tid & 7) * 4;            // col offset within tile

    u64 acc2[TH][2];
    {
        const float bv = bias[co];
        const u64 bp = pk(bv, bv);
        #pragma unroll
        for (int r = 0; r < TH; r++) {
            acc2[r][0] = bp;
            acc2[r][1] = bp;
        }
    }

    const float* wbase = sW + co * W_STRIDE;

    // sliding 3-row window; per row: even pairs p={(0,1),(2,3),(4,5)},
    // odd pairs q={(1,2),(3,4)}
    u64 wp[3][3];
    u64 wq[3][2];

#define LOADROW(wr, rowptr) do {                                         \
        ulonglong2 _t2 = *reinterpret_cast<const ulonglong2*>(rowptr);   \
        u64 _t1 = *reinterpret_cast<const u64*>((rowptr) + 4);           \
        wp[wr][0] = _t2.x; wp[wr][1] = _t2.y; wp[wr][2] = _t1;           \
        float _a0,_a1,_a2,_a3,_a4,_a5;                                   \
        upk(_a0,_a1,_t2.x); upk(_a2,_a3,_t2.y); upk(_a4,_a5,_t1);        \
        wq[wr][0] = pk(_a1,_a2); wq[wr][1] = pk(_a3,_a4);                \
    } while (0)

    #pragma unroll 1
    for (int ci = 0; ci < CH; ci++) {
        const float* ib = sIn + ci * (IN_H * IN_WP) + c0;

        // weights duplicated into (w,w) f32x2 pairs
        u64 w2[9];
        #pragma unroll
        for (int k = 0; k < 9; k++) {
            float wv = wbase[ci * 9 + k];
            w2[k] = pk(wv, wv);
        }

        LOADROW(0, ib);
        LOADROW(1, ib + IN_WP);

        #pragma unroll
        for (int r = 0; r < TH; r++) {
            LOADROW((r + 2) % 3, ib + (r + 2) * IN_WP);

            #pragma unroll
            for (int kh = 0; kh < 3; kh++) {
                const int wr = (r + kh) % 3;
                // out pair A0=(c0,c0+1), A1=(c0+2,c0+3)
                acc2[r][0] = f2fma(wp[wr][0], w2[kh*3+0], acc2[r][0]); // kw=0
                acc2[r][1] = f2fma(wp[wr][1], w2[kh*3+0], acc2[r][1]);
                acc2[r][0] = f2fma(wq[wr][0], w2[kh*3+1], acc2[r][0]); // kw=1
                acc2[r][1] = f2fma(wq[wr][1], w2[kh*3+1], acc2[r][1]);
                acc2[r][0] = f2fma(wp[wr][1], w2[kh*3+2], acc2[r][0]); // kw=2
                acc2[r][1] = f2fma(wp[wr][2], w2[kh*3+2], acc2[r][1]);
            }
        }
    }
#undef LOADROW

    // ---- store: 16B per row, contiguous 128B per 8-thread group ----
    #pragma unroll
    for (int r = 0; r < TH; r++) {
        float* op = out + ((size_t)(b * CH + co) * P + (r0 + r)) * P + (c0blk + c0);
        ulonglong2 v;
        v.x = acc2[r][0];
        v.y = acc2[r][1];
        *reinterpret_cast<ulonglong2*>(op) = v;
    }
}

extern "C" void kernel_launch(void* const* d_in, const int* in_sizes, int n_in,
                              void* d_out, int out_size)
{
    (void)in_sizes; (void)n_in; (void)out_size;
    const float* x    = (const float*)d_in[0];
    const float* rbuf = (const float*)d_in[1];
    const float* bbuf = (const float*)d_in[2];
    const float* Wt   = (const float*)d_in[3];
    const float* bias = (const float*)d_in[4];
    float* out = (float*)d_out;

    static bool inited = false;
    if (!inited) {
        cudaFuncSetAttribute(streamnet_conv3x3_kernel,
                             cudaFuncAttributeMaxDynamicSharedMemorySize, SMEM_BYTES);
        inited = true;
    }

    dim3 grid(P / TW, P / TH, BATCH);   // 8 x 32 x 8 = 2048 blocks
    streamnet_conv3x3_kernel<<<grid, 256, SMEM_BYTES>>>(x, rbuf, bbuf, Wt, bias, out);
}

// round 12
// speedup vs baseline: 1.4317x; 1.4317x over previous
#include <cuda_runtime.h>

// StreamNet_K3_S1: fused halo-concat + 3x3 VALID conv + bias.
// x:[8,32,256,256] rbuf:[8,32,256,2] bbuf:[8,32,2,258] W:[32,32,3,3] bias:[32]
// out:[8,32,256,256]
//
// R8: R6 scalar-FFMA compute path (f32x2 reverted — no pipe win on sm_103a),
// weights read from global via __ldg (L1/L2-resident, warp-broadcast) instead
// of smem. smem 83KB -> 46KB => 4 CTAs/SM (occ 24% -> ~48%).

#define BATCH 8
#define CH 32
#define P 256
#define PP (P + 2)

#define TH 8              // output rows per block
#define TW 32             // output cols per block
#define IN_H (TH + 2)     // 10 padded rows in tile
#define IN_W (TW + 2)     // 34 padded cols in tile
#define IN_WP 36          // smem row stride (floats), keeps 16B alignment

#define SMEM_IN_FLOATS (CH * IN_H * IN_WP)   // 11520
#define SMEM_BYTES (SMEM_IN_FLOATS * 4)      // 46080 B -> 4 CTAs/SM

__global__ __launch_bounds__(256, 4)
void streamnet_conv3x3_kernel(const float* __restrict__ x,
                              const float* __restrict__ rbuf,
                              const float* __restrict__ bbuf,
                              const float* __restrict__ Wt,
                              const float* __restrict__ bias,
                              float* __restrict__ out)
{
    extern __shared__ float smem[];
    float* sIn = smem;                       // [CH][IN_H][IN_WP]

    const int tid   = threadIdx.x;
    const int b     = blockIdx.z;
    const int r0    = blockIdx.y * TH;       // output row base
    const int c0blk = blockIdx.x * TW;       // output col base

    // ---- load padded input tile: 32ci x 10 x 34, halo-mapped ----
    for (int t = tid; t < CH * IN_H * IN_W; t += 256) {
        int ci   = t / (IN_H * IN_W);
        int rem  = t - ci * (IN_H * IN_W);
        int y    = rem / IN_W;
        int xcol = rem - y * IN_W;
        int pr   = r0 + y;                   // padded row  [0, 258)
        int pc   = c0blk + xcol;             // padded col  [0, 258)
        float v;
        if (pr < 2) {
            v = bbuf[((b * CH + ci) * 2 + pr) * PP + pc];
        } else {
            int xr = pr - 2;
            if (pc < 2) {
                v = rbuf[((b * CH + ci) * P + xr) * 2 + pc];
            } else {
                int xc = pc - 2;
                v = (xc == P - 1) ? 0.0f
                                  : x[((size_t)(b * CH + ci) * P + xr) * P + xc];
            }
        }
        sIn[ci * (IN_H * IN_WP) + y * IN_WP + xcol] = v;
    }
    __syncthreads();

    // ---- compute: each thread = 1 c_out, 8 rows x 4 cols ----
    const int co = tid >> 3;
    const int c0 = (tid & 7) * 4;            // col offset within tile

    float acc[TH][4];
    const float bv = __ldg(bias + co);
    #pragma unroll
    for (int r = 0; r < TH; r++)
        #pragma unroll
        for (int c = 0; c < 4; c++)
            acc[r][c] = bv;

    // weights straight from global: 36KB total, shared by all 2048 blocks ->
    // L1/L2 resident after wave 1; 8 threads/warp share each address.
    const float* wbase = Wt + co * (CH * 9);

    #pragma unroll 1
    for (int ci = 0; ci < CH; ci++) {
        const float* ib = sIn + ci * (IN_H * IN_WP) + c0;

        float w[9];
        #pragma unroll
        for (int k = 0; k < 9; k++) w[k] = __ldg(wbase + ci * 9 + k);

        // sliding 3-row x 6-col register window (16B-aligned -> LDS.128+LDS.64)
        float win[3][6];
        #pragma unroll
        for (int j = 0; j < 6; j++) {
            win[0][j] = ib[j];
            win[1][j] = ib[IN_WP + j];
        }

        #pragma unroll
        for (int r = 0; r < TH; r++) {
            const float* rowp = ib + (r + 2) * IN_WP;
            #pragma unroll
            for (int j = 0; j < 6; j++) win[(r + 2) % 3][j] = rowp[j];

            #pragma unroll
            for (int kh = 0; kh < 3; kh++) {
                const int wr = (r + kh) % 3;
                #pragma unroll
                for (int kw = 0; kw < 3; kw++) {
                    const float wv = w[kh * 3 + kw];
                    #pragma unroll
                    for (int c = 0; c < 4; c++)
                        acc[r][c] = fmaf(win[wr][c + kw], wv, acc[r][c]);
                }
            }
        }
    }

    // ---- store: float4 per row, contiguous 128B per 8-thread group ----
    #pragma unroll
    for (int r = 0; r < TH; r++) {
        float4 v = make_float4(acc[r][0], acc[r][1], acc[r][2], acc[r][3]);
        float* op = out + ((size_t)(b * CH + co) * P + (r0 + r)) * P + (c0blk + c0);
        *reinterpret_cast<float4*>(op) = v;
    }
}

extern "C" void kernel_launch(void* const* d_in, const int* in_sizes, int n_in,
                              void* d_out, int out_size)
{
    (void)in_sizes; (void)n_in; (void)out_size;
    const float* x    = (const float*)d_in[0];
    const float* rbuf = (const float*)d_in[1];
    const float* bbuf = (const float*)d_in[2];
    const float* Wt   = (const float*)d_in[3];
    const float* bias = (const float*)d_in[4];
    float* out = (float*)d_out;

    static bool inited = false;
    if (!inited) {
        cudaFuncSetAttribute(streamnet_conv3x3_kernel,
                             cudaFuncAttributeMaxDynamicSharedMemorySize, SMEM_BYTES);
        inited = true;
    }

    dim3 grid(P / TW, P / TH, BATCH);   // 8 x 32 x 8 = 2048 blocks
    streamnet_conv3x3_kernel<<<grid, 256, SMEM_BYTES>>>(x, rbuf, bbuf, Wt, bias, out);
}